// round 1
// baseline (speedup 1.0000x reference)
#include <cuda_runtime.h>

#define Bb    16
#define T     256
#define NJ    24
#define C     512
#define H     8
#define D     64
#define BATCH (Bb*NJ)     // 384
#define RTOT  (BATCH*T)   // 98304

// ---------------- scratch (static device memory; no allocations) ----------------
__device__ float g_q[(size_t)RTOT * C];
__device__ float g_k[(size_t)RTOT * C];
__device__ float g_v[(size_t)RTOT * C];
__device__ float g_mu[2 * RTOT];
__device__ float g_rstd[2 * RTOT];

// ---------------- kernel 1: per-row LN statistics ----------------
// rows 0..RTOT-1 -> x, rows RTOT..2*RTOT-1 -> cross_x
__global__ void ln_stats_kernel(const float* __restrict__ x,
                                const float* __restrict__ cx) {
    int warp = threadIdx.x >> 5, lane = threadIdx.x & 31;
    int row = blockIdx.x * 8 + warp;           // 0..2*RTOT-1
    const float* src = (row < RTOT) ? x : cx;
    int r  = (row < RTOT) ? row : row - RTOT;  // r = (bb*NJ + n)*T + t
    int bidx = r >> 8;                          // /T
    int t    = r & 255;
    int bb = bidx / NJ, n = bidx % NJ;
    const float4* p = (const float4*)(src + ((size_t)(bb * T + t) * NJ + n) * C);
    float s = 0.f, sq = 0.f;
#pragma unroll
    for (int i = 0; i < 4; i++) {
        float4 v = p[lane + 32 * i];
        s  += v.x + v.y + v.z + v.w;
        sq += v.x * v.x + v.y * v.y + v.z * v.z + v.w * v.w;
    }
#pragma unroll
    for (int o = 16; o; o >>= 1) {
        s  += __shfl_xor_sync(0xffffffffu, s, o);
        sq += __shfl_xor_sync(0xffffffffu, sq, o);
    }
    if (lane == 0) {
        float mu  = s * (1.0f / C);
        float var = sq * (1.0f / C) - mu * mu;
        g_mu[row]   = mu;
        g_rstd[row] = rsqrtf(var + 1e-5f);
    }
}

// ---------------- kernel 2: QKV projection GEMM with fused LayerNorm ----------------
// out[r,o] = sum_c LN(A[r,c]) * W[o,c]   (A gathered from (b,t,n,c) layout)
// BM=BN=128, BK=16, 256 threads, 8x8 microtile. grid.z selects q/k/v.
__global__ __launch_bounds__(256, 2) void qkv_gemm_kernel(
    const float* __restrict__ x, const float* __restrict__ cx,
    const float* __restrict__ gamma, const float* __restrict__ beta,
    const float* __restrict__ Wq, const float* __restrict__ Wk,
    const float* __restrict__ Wv) {
    __shared__ float As[16][132];
    __shared__ float Bs[16][132];
    __shared__ float sMu[128], sRs[128];

    int z = blockIdx.z;
    const float* A = (z == 0) ? x : cx;
    const float* W = (z == 0) ? Wq : (z == 1) ? Wk : Wv;
    float* dst     = (z == 0) ? g_q : (z == 1) ? g_k : g_v;
    int muOff      = (z == 0) ? 0 : RTOT;

    int r0 = blockIdx.y * 128;
    int o0 = blockIdx.x * 128;
    int tid = threadIdx.x;

    // all 128 rows of this tile share (bb, n); t runs t0..t0+127
    int bidx = r0 >> 8;     // row / T
    int t0   = r0 & 255;
    int bb = bidx / NJ, n = bidx % NJ;
    size_t baseA = ((size_t)(bb * T + t0) * NJ + n) * C;

    if (tid < 128) {
        sMu[tid] = g_mu[muOff + r0 + tid];
        sRs[tid] = g_rstd[muOff + r0 + tid];
    }
    __syncthreads();

    float acc[8][8];
#pragma unroll
    for (int i = 0; i < 8; i++)
#pragma unroll
        for (int j = 0; j < 8; j++) acc[i][j] = 0.f;

    int ty = tid >> 4, tx = tid & 15;

    for (int k0 = 0; k0 < C; k0 += 16) {
#pragma unroll
        for (int l = 0; l < 2; l++) {
            int idx = tid + l * 256;          // 0..511
            int rr = idx >> 2;                // 0..127
            int kk = (idx & 3) << 2;          // 0,4,8,12
            // A tile with fused LN
            float4 v = *(const float4*)(A + baseA + (size_t)rr * (NJ * C) + k0 + kk);
            float m = sMu[rr], rs = sRs[rr];
            float4 g  = *(const float4*)(gamma + k0 + kk);
            float4 be = *(const float4*)(beta + k0 + kk);
            As[kk + 0][rr] = (v.x - m) * rs * g.x + be.x;
            As[kk + 1][rr] = (v.y - m) * rs * g.y + be.y;
            As[kk + 2][rr] = (v.z - m) * rs * g.z + be.z;
            As[kk + 3][rr] = (v.w - m) * rs * g.w + be.w;
            // B tile (W rows, K-contiguous)
            float4 w = *(const float4*)(W + (size_t)(o0 + rr) * C + k0 + kk);
            Bs[kk + 0][rr] = w.x;
            Bs[kk + 1][rr] = w.y;
            Bs[kk + 2][rr] = w.z;
            Bs[kk + 3][rr] = w.w;
        }
        __syncthreads();
#pragma unroll
        for (int kk = 0; kk < 16; kk++) {
            float4 a0 = *(const float4*)&As[kk][ty * 8];
            float4 a1 = *(const float4*)&As[kk][ty * 8 + 4];
            float4 b0 = *(const float4*)&Bs[kk][tx * 8];
            float4 b1 = *(const float4*)&Bs[kk][tx * 8 + 4];
            float a[8]  = {a0.x, a0.y, a0.z, a0.w, a1.x, a1.y, a1.z, a1.w};
            float bv[8] = {b0.x, b0.y, b0.z, b0.w, b1.x, b1.y, b1.z, b1.w};
#pragma unroll
            for (int i = 0; i < 8; i++)
#pragma unroll
                for (int j = 0; j < 8; j++) acc[i][j] += a[i] * bv[j];
        }
        __syncthreads();
    }

#pragma unroll
    for (int i = 0; i < 8; i++) {
        size_t ro = (size_t)(r0 + ty * 8 + i) * C + o0 + tx * 8;
        *(float4*)(dst + ro)     = make_float4(acc[i][0], acc[i][1], acc[i][2], acc[i][3]);
        *(float4*)(dst + ro + 4) = make_float4(acc[i][4], acc[i][5], acc[i][6], acc[i][7]);
    }
}

// ---------------- kernel 3: attention + residual + output transpose ----------------
// one block per (batch, head); thread = one query; K,V slice in smem (128 KB)
__global__ __launch_bounds__(256, 1) void attn_kernel(const float* __restrict__ x,
                                                      float* __restrict__ out) {
    extern __shared__ float4 sm4[];
    float4* ks = sm4;             // 256*16 float4
    float4* vs = sm4 + 256 * 16;

    int bi = blockIdx.x / H;      // 0..383
    int h  = blockIdx.x % H;
    size_t base = (size_t)bi * T * C + h * D;   // element offset of (row 0) for this head
    const float4* kg = (const float4*)(g_k + base);
    const float4* vg = (const float4*)(g_v + base);
    int tid = threadIdx.x;

    for (int i = tid; i < 256 * 16; i += 256) {
        int r = i >> 4, c = i & 15;
        ks[i] = kg[(size_t)r * (C / 4) + c];
        vs[i] = vg[(size_t)r * (C / 4) + c];
    }
    __syncthreads();

    const float4* qg = (const float4*)(g_q + base + (size_t)tid * C);
    float4 q4[16];
#pragma unroll
    for (int i = 0; i < 16; i++) q4[i] = qg[i];

    float4 a4[16];
#pragma unroll
    for (int i = 0; i < 16; i++) a4[i] = make_float4(0.f, 0.f, 0.f, 0.f);
    float ssum = 0.f;

    for (int m = 0; m < 256; m++) {
        const float4* kr = ks + m * 16;
        float p0 = 0.f, p1 = 0.f, p2 = 0.f, p3 = 0.f;
#pragma unroll
        for (int i = 0; i < 16; i++) {
            float4 kv = kr[i];
            p0 += q4[i].x * kv.x;
            p1 += q4[i].y * kv.y;
            p2 += q4[i].z * kv.z;
            p3 += q4[i].w * kv.w;
        }
        float s = ((p0 + p1) + (p2 + p3)) * 0.125f;   // 1/sqrt(64)
        float e = __expf(s);                           // scores O(1); no max-shift needed
        ssum += e;
        const float4* vr = vs + m * 16;
#pragma unroll
        for (int i = 0; i < 16; i++) {
            float4 vv = vr[i];
            a4[i].x += e * vv.x;
            a4[i].y += e * vv.y;
            a4[i].z += e * vv.z;
            a4[i].w += e * vv.w;
        }
    }
    float inv = 1.0f / ssum;

    // residual + transpose back to (b, t, n, c)
    int bb = bi / NJ, n = bi % NJ;
    size_t oo = ((size_t)(bb * T + tid) * NJ + n) * C + h * D;
    const float4* xg = (const float4*)(x + oo);
    float4* og = (float4*)(out + oo);
#pragma unroll
    for (int i = 0; i < 16; i++) {
        float4 xv = xg[i];
        og[i] = make_float4(xv.x + a4[i].x * inv, xv.y + a4[i].y * inv,
                            xv.z + a4[i].z * inv, xv.w + a4[i].w * inv);
    }
}

// ---------------- launch ----------------
extern "C" void kernel_launch(void* const* d_in, const int* in_sizes, int n_in,
                              void* d_out, int out_size) {
    const float* x     = (const float*)d_in[0];
    const float* cx    = (const float*)d_in[1];
    const float* gamma = (const float*)d_in[2];
    const float* beta  = (const float*)d_in[3];
    const float* Wq    = (const float*)d_in[4];
    const float* Wk    = (const float*)d_in[5];
    const float* Wv    = (const float*)d_in[6];
    float* out = (float*)d_out;

    cudaFuncSetAttribute(attn_kernel, cudaFuncAttributeMaxDynamicSharedMemorySize,
                         131072);

    ln_stats_kernel<<<2 * RTOT / 8, 256>>>(x, cx);

    dim3 gg(C / 128, RTOT / 128, 3);
    qkv_gemm_kernel<<<gg, 256>>>(x, cx, gamma, beta, Wq, Wk, Wv);

    attn_kernel<<<BATCH * H, 256, 131072>>>(x, out);
}